// round 6
// baseline (speedup 1.0000x reference)
#include <cuda_runtime.h>
#include <math.h>

// Problem constants (fixed by the reference)
#define BB 4
#define SS 1024
#define DD 1024
#define HH 16
#define HD 64

// Scratch (allocation-free rule: __device__ globals)
__device__ float g_Q[BB*HH*SS*HD];   // [B,H,S,Hd]
__device__ float g_K[BB*HH*SS*HD];
__device__ float g_V[BB*HH*SS*HD];
__device__ float g_ctx[BB*SS*DD];    // [B,S,D]

// ---------------------------------------------------------------------------
// TF32 tensor-core SGEMM with 3xTF32 hi/lo split (fp32-level accuracy).
// Y = X @ W^T, M=4096(or 4096), N=1024, K=1024.
// Block 128x128x16, 128 threads (4 warps), warp tile 64x64, mma.m16n8k8.
// ---------------------------------------------------------------------------
#define GBM 128
#define GBN 128
#define GBK 16
#define LDF 20   // padded smem row stride (floats); conflict-free for frag reads

__device__ __forceinline__ float f2tf(float x) {
    unsigned u;
    asm("cvt.rna.tf32.f32 %0, %1;" : "=r"(u) : "f"(x));
    return __uint_as_float(u);
}

__device__ __forceinline__ void mma8(float c[4], const float a[4], const float b[2]) {
    asm volatile(
        "mma.sync.aligned.m16n8k8.row.col.f32.tf32.tf32.f32 "
        "{%0,%1,%2,%3}, {%4,%5,%6,%7}, {%8,%9}, {%0,%1,%2,%3};"
        : "+f"(c[0]), "+f"(c[1]), "+f"(c[2]), "+f"(c[3])
        : "r"(__float_as_uint(a[0])), "r"(__float_as_uint(a[1])),
          "r"(__float_as_uint(a[2])), "r"(__float_as_uint(a[3])),
          "r"(__float_as_uint(b[0])), "r"(__float_as_uint(b[1])));
}

template<int MODE>  // 0 = scatter to [B,H,S,Hd], 1 = plain row-major [M,N]
__device__ __forceinline__ void gemm_tf32(const float* __restrict__ X,
                                          const float* __restrict__ W,
                                          float* __restrict__ Y)
{
    __shared__ float smbuf[4 * GBM * LDF];   // Ah, Al, Bh, Bl = 40960 bytes
    float* Ah = smbuf;
    float* Al = smbuf + GBM * LDF;
    float* Bh = smbuf + 2 * GBM * LDF;
    float* Bl = smbuf + 3 * GBM * LDF;

    const int K = 1024, N = 1024;
    int t = threadIdx.x;
    int lane = t & 31, warp = t >> 5;
    int g = lane >> 2, c = lane & 3;      // groupID / threadID-in-group
    int wm = warp >> 1, wn = warp & 1;    // 2x2 warp grid, 64x64 per warp
    int m0 = blockIdx.y * GBM, n0 = blockIdx.x * GBN;

    float acc[4][8][4];
    #pragma unroll
    for (int mi = 0; mi < 4; mi++)
        #pragma unroll
        for (int ni = 0; ni < 8; ni++)
            #pragma unroll
            for (int r = 0; r < 4; r++) acc[mi][ni][r] = 0.f;

    for (int k0 = 0; k0 < K; k0 += GBK) {
        __syncthreads();   // previous compute finished before overwrite
        // Stage A and B tiles, converting fp32 -> (hi, lo) tf32 pair.
        // fid -> row = fid>>2, k-offset = (fid&3)*4 : coalesced 64B per row.
        #pragma unroll
        for (int seg = 0; seg < 4; seg++) {
            int fid = t + seg * 128;
            int row = fid >> 2;
            int jc = (fid & 3) * 4;
            float4 fa = *(const float4*)&X[(size_t)(m0 + row) * K + k0 + jc];
            float4 h, l;
            h.x = f2tf(fa.x); l.x = f2tf(fa.x - h.x);
            h.y = f2tf(fa.y); l.y = f2tf(fa.y - h.y);
            h.z = f2tf(fa.z); l.z = f2tf(fa.z - h.z);
            h.w = f2tf(fa.w); l.w = f2tf(fa.w - h.w);
            *(float4*)&Ah[row * LDF + jc] = h;
            *(float4*)&Al[row * LDF + jc] = l;
            float4 fb = *(const float4*)&W[(size_t)(n0 + row) * K + k0 + jc];
            float4 hb, lb;
            hb.x = f2tf(fb.x); lb.x = f2tf(fb.x - hb.x);
            hb.y = f2tf(fb.y); lb.y = f2tf(fb.y - hb.y);
            hb.z = f2tf(fb.z); lb.z = f2tf(fb.z - hb.z);
            hb.w = f2tf(fb.w); lb.w = f2tf(fb.w - hb.w);
            *(float4*)&Bh[row * LDF + jc] = hb;
            *(float4*)&Bl[row * LDF + jc] = lb;
        }
        __syncthreads();

        #pragma unroll
        for (int ks = 0; ks < 2; ks++) {
            // A fragments: m16n8k8 layout. a0:(g,c) a1:(g+8,c) a2:(g,c+4) a3:(g+8,c+4)
            float ah[4][4], al[4][4];
            #pragma unroll
            for (int mi = 0; mi < 4; mi++) {
                int rowb = (wm * 4 + mi) * 16 + g;
                #pragma unroll
                for (int r = 0; r < 4; r++) {
                    int idx = (rowb + (r & 1) * 8) * LDF + ks * 8 + c + (r >> 1) * 4;
                    ah[mi][r] = Ah[idx];
                    al[mi][r] = Al[idx];
                }
            }
            // B fragments: b0:(k=c, n=g) b1:(k=c+4, n=g)
            float bh[8][2], bl[8][2];
            #pragma unroll
            for (int ni = 0; ni < 8; ni++) {
                int rowb = (wn * 8 + ni) * 8 + g;
                #pragma unroll
                for (int r = 0; r < 2; r++) {
                    int idx = rowb * LDF + ks * 8 + c + r * 4;
                    bh[ni][r] = Bh[idx];
                    bl[ni][r] = Bl[idx];
                }
            }
            #pragma unroll
            for (int mi = 0; mi < 4; mi++)
                #pragma unroll
                for (int ni = 0; ni < 8; ni++) {
                    mma8(acc[mi][ni], ah[mi], bh[ni]);   // hi*hi
                    mma8(acc[mi][ni], ah[mi], bl[ni]);   // hi*lo
                    mma8(acc[mi][ni], al[mi], bh[ni]);   // lo*hi
                }
        }
    }

    // Epilogue. C frag: c0:(g, 2c) c1:(g, 2c+1) c2:(g+8, 2c) c3:(g+8, 2c+1)
    #pragma unroll
    for (int mi = 0; mi < 4; mi++) {
        #pragma unroll
        for (int half = 0; half < 2; half++) {
            int m = m0 + (wm * 4 + mi) * 16 + g + half * 8;
            #pragma unroll
            for (int ni = 0; ni < 8; ni++) {
                int n = n0 + (wn * 8 + ni) * 8 + c * 2;
                float2 val;
                val.x = acc[mi][ni][half * 2];
                val.y = acc[mi][ni][half * 2 + 1];
                if (MODE == 0) {
                    int b = m >> 10, s = m & 1023, h = n >> 6, d = n & 63;
                    *(float2*)&Y[(((size_t)(b * HH + h)) * SS + s) * HD + d] = val;
                } else {
                    *(float2*)&Y[(size_t)m * N + n] = val;
                }
            }
        }
    }
}

__global__ __launch_bounds__(128, 2) void proj_kernel(const float* __restrict__ q,
                                                      const float* __restrict__ k,
                                                      const float* __restrict__ v,
                                                      const float* __restrict__ Wq)
{
    const float* X = (blockIdx.z == 0) ? q : (blockIdx.z == 1) ? k : v;
    float* Y = (blockIdx.z == 0) ? g_Q : (blockIdx.z == 1) ? g_K : g_V;
    gemm_tf32<0>(X, Wq, Y);
}

__global__ __launch_bounds__(128, 2) void out_kernel(const float* __restrict__ Wout,
                                                     float* __restrict__ out)
{
    gemm_tf32<1>(g_ctx, Wout, out);
}

// ---------------------------------------------------------------------------
// Flash attention with ALiBi bias.  Per block: one (b,h), 64 query rows.
// Tiles of 64 keys; online softmax; P routed through smem (reuses K buffer).
// ---------------------------------------------------------------------------
#define LDA 68   // padded leading dim (floats); 68*4 bytes keeps 16B alignment

__global__ __launch_bounds__(256) void attn_kernel(const int* __restrict__ mask)
{
    extern __shared__ float sm[];
    float* Qt  = sm;               // [64 dims][LDA rows]  (Q transposed)
    float* KPt = sm + 64*LDA;      // K transposed, then P transposed [key][row]
    float* Vs  = sm + 2*64*LDA;    // [key][LDA dims]
    __shared__ float maskneg[64];  // 0 or nonzero flag (-1e9) per key

    int tid = threadIdx.x;
    int tx = tid & 15, ty = tid >> 4;
    int bh = blockIdx.y;
    int b = bh >> 4, h = bh & 15;
    int q0 = blockIdx.x * 64;
    const float slope = exp2f(-0.5f * (float)(h + 1));

    const float* Qg = g_Q + ((size_t)bh * SS + q0) * HD;
    const float* Kg = g_K + (size_t)bh * SS * HD;
    const float* Vg = g_V + (size_t)bh * SS * HD;

    // Load Q tile transposed: Qt[dim][row]
    #pragma unroll
    for (int l = 0; l < 4; l++) {
        int idx = tid + l * 256;
        int r = idx >> 4;
        int c = (idx & 15) * 4;
        float4 f = *(const float4*)&Qg[r*HD + c];
        Qt[(c+0)*LDA + r] = f.x; Qt[(c+1)*LDA + r] = f.y;
        Qt[(c+2)*LDA + r] = f.z; Qt[(c+3)*LDA + r] = f.w;
    }

    float m_run[4], l_run[4], o[4][4];
    #pragma unroll
    for (int i = 0; i < 4; i++) {
        m_run[i] = -1e30f; l_run[i] = 0.f;
        #pragma unroll
        for (int j = 0; j < 4; j++) o[i][j] = 0.f;
    }

    #pragma unroll 1
    for (int kt = 0; kt < 16; kt++) {
        int kbase = kt * 64;
        // Load K (transposed) and V (direct) tiles
        #pragma unroll
        for (int l = 0; l < 4; l++) {
            int idx = tid + l * 256;
            int r = idx >> 4;
            int c = (idx & 15) * 4;
            float4 f = *(const float4*)&Kg[(size_t)(kbase + r)*HD + c];
            KPt[(c+0)*LDA + r] = f.x; KPt[(c+1)*LDA + r] = f.y;
            KPt[(c+2)*LDA + r] = f.z; KPt[(c+3)*LDA + r] = f.w;
            float4 g = *(const float4*)&Vg[(size_t)(kbase + r)*HD + c];
            *(float4*)&Vs[r*LDA + c] = g;
        }
        if (tid < 64)
            maskneg[tid] = (mask[b*SS + kbase + tid] == 0) ? -1e9f : 0.f;
        __syncthreads();

        // S = Q K^T  (4x4 per thread)
        float s[4][4];
        #pragma unroll
        for (int i = 0; i < 4; i++)
            #pragma unroll
            for (int j = 0; j < 4; j++) s[i][j] = 0.f;

        #pragma unroll 16
        for (int kk = 0; kk < 64; kk++) {
            float4 a  = *(const float4*)&Qt[kk*LDA + ty*4];
            float4 bb = *(const float4*)&KPt[kk*LDA + tx*4];
            float av[4] = {a.x, a.y, a.z, a.w};
            float bv[4] = {bb.x, bb.y, bb.z, bb.w};
            #pragma unroll
            for (int i = 0; i < 4; i++)
                #pragma unroll
                for (int j = 0; j < 4; j++)
                    s[i][j] = fmaf(av[i], bv[j], s[i][j]);
        }

        // ALiBi bias + mask
        #pragma unroll
        for (int i = 0; i < 4; i++) {
            int qi = q0 + ty*4 + i;
            #pragma unroll
            for (int j = 0; j < 4; j++) {
                int kj = kbase + tx*4 + j;
                if (kj <= qi) s[i][j] += slope * (float)(kj - qi);
                if (maskneg[tx*4 + j] != 0.f) s[i][j] = -1e9f;
            }
        }

        // Online softmax update (rows spread across 16 lanes: tx groups)
        #pragma unroll
        for (int i = 0; i < 4; i++) {
            float mt = fmaxf(fmaxf(s[i][0], s[i][1]), fmaxf(s[i][2], s[i][3]));
            #pragma unroll
            for (int off = 1; off < 16; off <<= 1)
                mt = fmaxf(mt, __shfl_xor_sync(0xffffffffu, mt, off));
            float nm = fmaxf(m_run[i], mt);
            float corr = __expf(m_run[i] - nm);
            float rs = 0.f;
            #pragma unroll
            for (int j = 0; j < 4; j++) {
                s[i][j] = __expf(s[i][j] - nm);
                rs += s[i][j];
            }
            #pragma unroll
            for (int off = 1; off < 16; off <<= 1)
                rs += __shfl_xor_sync(0xffffffffu, rs, off);
            l_run[i] = l_run[i] * corr + rs;
            m_run[i] = nm;
            #pragma unroll
            for (int j = 0; j < 4; j++) o[i][j] *= corr;
        }

        __syncthreads();  // done reading KPt as K
        // Write P transposed: KPt[key][row]
        #pragma unroll
        for (int i = 0; i < 4; i++)
            #pragma unroll
            for (int j = 0; j < 4; j++)
                KPt[(tx*4 + j)*LDA + ty*4 + i] = s[i][j];
        __syncthreads();

        // O += P V
        #pragma unroll 16
        for (int kk = 0; kk < 64; kk++) {
            float4 p  = *(const float4*)&KPt[kk*LDA + ty*4];
            float4 vv = *(const float4*)&Vs[kk*LDA + tx*4];
            float pv[4] = {p.x, p.y, p.z, p.w};
            float vvv[4] = {vv.x, vv.y, vv.z, vv.w};
            #pragma unroll
            for (int i = 0; i < 4; i++)
                #pragma unroll
                for (int j = 0; j < 4; j++)
                    o[i][j] = fmaf(pv[i], vvv[j], o[i][j]);
        }
        __syncthreads();  // before next tile overwrites KPt/Vs
    }

    // Normalize and write ctx in [B,S,D] layout
    #pragma unroll
    for (int i = 0; i < 4; i++) {
        float inv = 1.f / l_run[i];
        int srow = q0 + ty*4 + i;
        #pragma unroll
        for (int j = 0; j < 4; j++)
            g_ctx[((size_t)b * SS + srow) * DD + h*HD + tx*4 + j] = o[i][j] * inv;
    }
}

// ---------------------------------------------------------------------------
extern "C" void kernel_launch(void* const* d_in, const int* in_sizes, int n_in,
                              void* d_out, int out_size)
{
    const float* q    = (const float*)d_in[0];
    const float* k    = (const float*)d_in[1];
    const float* v    = (const float*)d_in[2];
    const int*   mask = (const int*)d_in[3];
    const float* Wq   = (const float*)d_in[4];
    const float* Wout = (const float*)d_in[5];
    float* out = (float*)d_out;

    const int attn_smem = 3 * 64 * LDA * (int)sizeof(float);  // 52224 bytes
    cudaFuncSetAttribute(attn_kernel, cudaFuncAttributeMaxDynamicSharedMemorySize,
                         attn_smem);

    // Q/K/V projections (all use Wq, faithful to the reference "bug")
    proj_kernel<<<dim3(8, 32, 3), 128>>>(q, k, v, Wq);
    // Flash attention with ALiBi
    attn_kernel<<<dim3(16, 64), 256, attn_smem>>>(mask);
    // Output projection
    out_kernel<<<dim3(8, 32), 128>>>(Wout, out);
}

// round 10
// speedup vs baseline: 1.8824x; 1.8824x over previous
#include <cuda_runtime.h>
#include <cuda_bf16.h>
#include <math.h>

// Problem constants (fixed by the reference)
#define BB 4
#define SS 1024
#define DD 1024
#define HH 16
#define HD 64

// ---------------------------------------------------------------------------
// Device scratch (allocation-free rule: __device__ globals)
// ---------------------------------------------------------------------------
__device__ float g_Q[BB*HH*SS*HD];   // [B,H,S,Hd] fp32 (attention inputs)
__device__ float g_K[BB*HH*SS*HD];
__device__ float g_V[BB*HH*SS*HD];

// bf16 hi/lo split operands for mma.sync GEMMs
__device__ __nv_bfloat16 g_xh[3*4096*1024];   // q,k,v hi
__device__ __nv_bfloat16 g_xl[3*4096*1024];   // q,k,v lo
__device__ __nv_bfloat16 g_wqh[1024*1024];
__device__ __nv_bfloat16 g_wql[1024*1024];
__device__ __nv_bfloat16 g_woh[1024*1024];
__device__ __nv_bfloat16 g_wol[1024*1024];
__device__ __nv_bfloat16 g_ctxh[4096*1024];   // attention output hi
__device__ __nv_bfloat16 g_ctxl[4096*1024];   // attention output lo

// ---------------------------------------------------------------------------
// Helpers
// ---------------------------------------------------------------------------
__device__ __forceinline__ unsigned smem_u32(const void* p) {
    unsigned a;
    asm("{ .reg .u64 t; cvta.to.shared.u64 t, %1; cvt.u32.u64 %0, t; }"
        : "=r"(a) : "l"(p));
    return a;
}

__device__ __forceinline__ void cp16(unsigned saddr, const void* gaddr) {
    asm volatile("cp.async.cg.shared.global [%0], [%1], 16;"
                 :: "r"(saddr), "l"(gaddr));
}
#define CP_COMMIT() asm volatile("cp.async.commit_group;" ::: "memory")
#define CP_WAIT0()  asm volatile("cp.async.wait_group 0;" ::: "memory")

// bf16 MMA m16n8k16, fp32 accumulate (legacy tensor path; compiles for sm_103)
__device__ __forceinline__ void mma16(float c[4], const unsigned a[4],
                                      const unsigned b[2]) {
    asm volatile(
        "mma.sync.aligned.m16n8k16.row.col.f32.bf16.bf16.f32 "
        "{%0,%1,%2,%3},{%4,%5,%6,%7},{%8,%9},{%0,%1,%2,%3};"
        : "+f"(c[0]), "+f"(c[1]), "+f"(c[2]), "+f"(c[3])
        : "r"(a[0]), "r"(a[1]), "r"(a[2]), "r"(a[3]), "r"(b[0]), "r"(b[1]));
}

// ---------------------------------------------------------------------------
// bf16 hi/lo split GEMM: Y = A @ B^T  (M x 1024) @ (1024 x 1024)^T
// Block 128x128, BK=32, 512 threads (16 warps, 4x4 grid, warp tile 32x32),
// cp.async double-buffered. 3 MMA passes: AhBh + AhBl + AlBh.
// ---------------------------------------------------------------------------
#define LDH 40                      // bf16 halves per smem row (32 + 8 pad)
#define LDW 20                      // 32-bit words per smem row
#define MATB (128*LDH*2)            // 10240 bytes per matrix tile
#define STAGEB (4*MATB)             // Ah,Al,Bh,Bl = 40960 bytes per stage
#define MMSMEM (2*STAGEB)           // 81920 bytes

template<int MODE>  // 0 = scatter fp32 to [B,H,S,Hd]; 1 = row-major [M,1024]
__device__ __forceinline__ void mm_body(const __nv_bfloat16* __restrict__ Ahp,
                                        const __nv_bfloat16* __restrict__ Alp,
                                        const __nv_bfloat16* __restrict__ Bhp,
                                        const __nv_bfloat16* __restrict__ Blp,
                                        float* __restrict__ Y)
{
    extern __shared__ char smc[];
    const unsigned sb = smem_u32(smc);
    const int tid = threadIdx.x;
    const int lane = tid & 31, warp = tid >> 5;
    const int g = lane >> 2, c = lane & 3;
    const int wm = warp >> 2, wn = warp & 3;
    const int m0 = blockIdx.y * 128, n0 = blockIdx.x * 128;

    float acc[2][4][4];
    #pragma unroll
    for (int mi = 0; mi < 2; mi++)
        #pragma unroll
        for (int ni = 0; ni < 4; ni++)
            #pragma unroll
            for (int r = 0; r < 4; r++) acc[mi][ni][r] = 0.f;

    // Staging assignment: 4 groups of 128 threads, one matrix each.
    const int mat = tid >> 7;         // 0=Ah 1=Al 2=Bh 3=Bl
    const int t = tid & 127;
    const __nv_bfloat16* gp = (mat == 0) ? Ahp : (mat == 1) ? Alp
                            : (mat == 2) ? Bhp : Blp;
    const int rowoff = (mat >= 2) ? n0 : m0;
    const unsigned smat = (unsigned)(mat * MATB);

    auto stage = [&](int kc, int buf) {
        #pragma unroll
        for (int i = 0; i < 4; i++) {
            int id = t + i * 128;
            int row = id >> 2, seg = id & 3;
            const void* ga = gp + (size_t)(rowoff + row) * 1024 + kc * 32 + seg * 8;
            unsigned sa = sb + (unsigned)buf * STAGEB + smat
                        + (unsigned)(row * (LDH * 2) + seg * 16);
            cp16(sa, ga);
        }
        CP_COMMIT();
    };

    stage(0, 0);

    for (int kc = 0; kc < 32; kc++) {
        CP_WAIT0();
        __syncthreads();
        if (kc + 1 < 32) stage(kc + 1, (kc + 1) & 1);

        const unsigned* Ahw = (const unsigned*)(smc + (size_t)(kc & 1) * STAGEB);
        const unsigned* Alw = Ahw + MATB / 4;
        const unsigned* Bhw = Ahw + 2 * (MATB / 4);
        const unsigned* Blw = Ahw + 3 * (MATB / 4);

        #pragma unroll
        for (int ks = 0; ks < 2; ks++) {
            unsigned ah[2][4], al[2][4];
            #pragma unroll
            for (int mi = 0; mi < 2; mi++) {
                int rb = wm * 32 + mi * 16;
                int w0 = (rb + g) * LDW + ks * 8 + c;
                int w1 = (rb + 8 + g) * LDW + ks * 8 + c;
                ah[mi][0] = Ahw[w0];     ah[mi][1] = Ahw[w1];
                ah[mi][2] = Ahw[w0 + 4]; ah[mi][3] = Ahw[w1 + 4];
                al[mi][0] = Alw[w0];     al[mi][1] = Alw[w1];
                al[mi][2] = Alw[w0 + 4]; al[mi][3] = Alw[w1 + 4];
            }
            unsigned bh[4][2], bl[4][2];
            #pragma unroll
            for (int ni = 0; ni < 4; ni++) {
                int nr = wn * 32 + ni * 8 + g;
                int w = nr * LDW + ks * 8 + c;
                bh[ni][0] = Bhw[w]; bh[ni][1] = Bhw[w + 4];
                bl[ni][0] = Blw[w]; bl[ni][1] = Blw[w + 4];
            }
            #pragma unroll
            for (int mi = 0; mi < 2; mi++)
                #pragma unroll
                for (int ni = 0; ni < 4; ni++) {
                    mma16(acc[mi][ni], ah[mi], bh[ni]);   // hi*hi
                    mma16(acc[mi][ni], ah[mi], bl[ni]);   // hi*lo
                    mma16(acc[mi][ni], al[mi], bh[ni]);   // lo*hi
                }
        }
    }

    // Epilogue. C frag: c0,c1=(g,2c),(g,2c+1); c2,c3=(g+8,2c),(g+8,2c+1)
    #pragma unroll
    for (int mi = 0; mi < 2; mi++) {
        #pragma unroll
        for (int half = 0; half < 2; half++) {
            int m = m0 + wm * 32 + mi * 16 + g + half * 8;
            #pragma unroll
            for (int ni = 0; ni < 4; ni++) {
                int n = n0 + wn * 32 + ni * 8 + c * 2;
                float2 val;
                val.x = acc[mi][ni][half * 2];
                val.y = acc[mi][ni][half * 2 + 1];
                if (MODE == 0) {
                    int b = m >> 10, s = m & 1023, h = n >> 6, d = n & 63;
                    *(float2*)&Y[(((size_t)(b * HH + h)) * SS + s) * HD + d] = val;
                } else {
                    *(float2*)&Y[(size_t)m * 1024 + n] = val;
                }
            }
        }
    }
}

__global__ __launch_bounds__(512, 1) void proj_mm()
{
    int z = blockIdx.z;
    float* Y = (z == 0) ? g_Q : (z == 1) ? g_K : g_V;
    mm_body<0>(g_xh + (size_t)z * 4194304, g_xl + (size_t)z * 4194304,
               g_wqh, g_wql, Y);
}

__global__ __launch_bounds__(512, 1) void out_mm(float* __restrict__ out)
{
    mm_body<1>(g_ctxh, g_ctxl, g_woh, g_wol, out);
}

// ---------------------------------------------------------------------------
// fp32 -> bf16 hi/lo conversion (one float4 per thread)
// ---------------------------------------------------------------------------
__device__ __forceinline__ void hilo(float x, unsigned short& h, unsigned short& l) {
    __nv_bfloat16 hb = __float2bfloat16_rn(x);
    h = *reinterpret_cast<unsigned short*>(&hb);
    __nv_bfloat16 lb = __float2bfloat16_rn(x - __bfloat162float(hb));
    l = *reinterpret_cast<unsigned short*>(&lb);
}

__global__ __launch_bounds__(256) void conv_kernel(const float4* __restrict__ src,
                                                   int sel, int n4)
{
    int idx = blockIdx.x * 256 + threadIdx.x;
    if (idx >= n4) return;
    __nv_bfloat16 *hi, *lo;
    if (sel < 3)      { hi = g_xh + (size_t)sel * 4194304; lo = g_xl + (size_t)sel * 4194304; }
    else if (sel == 3){ hi = g_wqh; lo = g_wql; }
    else              { hi = g_woh; lo = g_wol; }
    float4 f = src[idx];
    unsigned short h0,h1,h2,h3,l0,l1,l2,l3;
    hilo(f.x, h0, l0); hilo(f.y, h1, l1);
    hilo(f.z, h2, l2); hilo(f.w, h3, l3);
    uint2 H, L;
    H.x = (unsigned)h0 | ((unsigned)h1 << 16);
    H.y = (unsigned)h2 | ((unsigned)h3 << 16);
    L.x = (unsigned)l0 | ((unsigned)l1 << 16);
    L.y = (unsigned)l2 | ((unsigned)l3 << 16);
    ((uint2*)hi)[idx] = H;
    ((uint2*)lo)[idx] = L;
}

// ---------------------------------------------------------------------------
// Flash attention with ALiBi bias (fp32 mainloop; epilogue emits bf16 hi/lo).
// ---------------------------------------------------------------------------
#define LDA 68

__global__ __launch_bounds__(256) void attn_kernel(const int* __restrict__ mask)
{
    extern __shared__ float sm[];
    float* Qt  = sm;               // [64 dims][LDA rows]  (Q transposed)
    float* KPt = sm + 64*LDA;      // K transposed, then P transposed [key][row]
    float* Vs  = sm + 2*64*LDA;    // [key][LDA dims]
    __shared__ float maskneg[64];

    int tid = threadIdx.x;
    int tx = tid & 15, ty = tid >> 4;
    int bh = blockIdx.y;
    int b = bh >> 4, hh = bh & 15;
    int q0 = blockIdx.x * 64;
    const float slope = exp2f(-0.5f * (float)(hh + 1));

    const float* Qg = g_Q + ((size_t)bh * SS + q0) * HD;
    const float* Kg = g_K + (size_t)bh * SS * HD;
    const float* Vg = g_V + (size_t)bh * SS * HD;

    #pragma unroll
    for (int l = 0; l < 4; l++) {
        int idx = tid + l * 256;
        int r = idx >> 4;
        int c = (idx & 15) * 4;
        float4 f = *(const float4*)&Qg[r*HD + c];
        Qt[(c+0)*LDA + r] = f.x; Qt[(c+1)*LDA + r] = f.y;
        Qt[(c+2)*LDA + r] = f.z; Qt[(c+3)*LDA + r] = f.w;
    }

    float m_run[4], l_run[4], o[4][4];
    #pragma unroll
    for (int i = 0; i < 4; i++) {
        m_run[i] = -1e30f; l_run[i] = 0.f;
        #pragma unroll
        for (int j = 0; j < 4; j++) o[i][j] = 0.f;
    }

    #pragma unroll 1
    for (int kt = 0; kt < 16; kt++) {
        int kbase = kt * 64;
        #pragma unroll
        for (int l = 0; l < 4; l++) {
            int idx = tid + l * 256;
            int r = idx >> 4;
            int c = (idx & 15) * 4;
            float4 f = *(const float4*)&Kg[(size_t)(kbase + r)*HD + c];
            KPt[(c+0)*LDA + r] = f.x; KPt[(c+1)*LDA + r] = f.y;
            KPt[(c+2)*LDA + r] = f.z; KPt[(c+3)*LDA + r] = f.w;
            float4 g = *(const float4*)&Vg[(size_t)(kbase + r)*HD + c];
            *(float4*)&Vs[r*LDA + c] = g;
        }
        if (tid < 64)
            maskneg[tid] = (mask[b*SS + kbase + tid] == 0) ? -1e9f : 0.f;
        __syncthreads();

        float s[4][4];
        #pragma unroll
        for (int i = 0; i < 4; i++)
            #pragma unroll
            for (int j = 0; j < 4; j++) s[i][j] = 0.f;

        #pragma unroll 16
        for (int kk = 0; kk < 64; kk++) {
            float4 a  = *(const float4*)&Qt[kk*LDA + ty*4];
            float4 bb = *(const float4*)&KPt[kk*LDA + tx*4];
            float av[4] = {a.x, a.y, a.z, a.w};
            float bv[4] = {bb.x, bb.y, bb.z, bb.w};
            #pragma unroll
            for (int i = 0; i < 4; i++)
                #pragma unroll
                for (int j = 0; j < 4; j++)
                    s[i][j] = fmaf(av[i], bv[j], s[i][j]);
        }

        #pragma unroll
        for (int i = 0; i < 4; i++) {
            int qi = q0 + ty*4 + i;
            #pragma unroll
            for (int j = 0; j < 4; j++) {
                int kj = kbase + tx*4 + j;
                if (kj <= qi) s[i][j] += slope * (float)(kj - qi);
                if (maskneg[tx*4 + j] != 0.f) s[i][j] = -1e9f;
            }
        }

        #pragma unroll
        for (int i = 0; i < 4; i++) {
            float mt = fmaxf(fmaxf(s[i][0], s[i][1]), fmaxf(s[i][2], s[i][3]));
            #pragma unroll
            for (int off = 1; off < 16; off <<= 1)
                mt = fmaxf(mt, __shfl_xor_sync(0xffffffffu, mt, off));
            float nm = fmaxf(m_run[i], mt);
            float corr = __expf(m_run[i] - nm);
            float rs = 0.f;
            #pragma unroll
            for (int j = 0; j < 4; j++) {
                s[i][j] = __expf(s[i][j] - nm);
                rs += s[i][j];
            }
            #pragma unroll
            for (int off = 1; off < 16; off <<= 1)
                rs += __shfl_xor_sync(0xffffffffu, rs, off);
            l_run[i] = l_run[i] * corr + rs;
            m_run[i] = nm;
            #pragma unroll
            for (int j = 0; j < 4; j++) o[i][j] *= corr;
        }

        __syncthreads();
        #pragma unroll
        for (int i = 0; i < 4; i++)
            #pragma unroll
            for (int j = 0; j < 4; j++)
                KPt[(tx*4 + j)*LDA + ty*4 + i] = s[i][j];
        __syncthreads();

        #pragma unroll 16
        for (int kk = 0; kk < 64; kk++) {
            float4 p  = *(const float4*)&KPt[kk*LDA + ty*4];
            float4 vv = *(const float4*)&Vs[kk*LDA + tx*4];
            float pv[4] = {p.x, p.y, p.z, p.w};
            float vvv[4] = {vv.x, vv.y, vv.z, vv.w};
            #pragma unroll
            for (int i = 0; i < 4; i++)
                #pragma unroll
                for (int j = 0; j < 4; j++)
                    o[i][j] = fmaf(pv[i], vvv[j], o[i][j]);
        }
        __syncthreads();
    }

    // Normalize; write ctx directly as bf16 hi/lo in [B,S,D] layout.
    #pragma unroll
    for (int i = 0; i < 4; i++) {
        float inv = 1.f / l_run[i];
        int srow = q0 + ty*4 + i;
        #pragma unroll
        for (int j = 0; j < 4; j++) {
            float val = o[i][j] * inv;
            size_t off = ((size_t)b * SS + srow) * DD + hh*HD + tx*4 + j;
            __nv_bfloat16 hb = __float2bfloat16_rn(val);
            g_ctxh[off] = hb;
            g_ctxl[off] = __float2bfloat16_rn(val - __bfloat162float(hb));
        }
    }
}

// ---------------------------------------------------------------------------
extern "C" void kernel_launch(void* const* d_in, const int* in_sizes, int n_in,
                              void* d_out, int out_size)
{
    const float* q    = (const float*)d_in[0];
    const float* k    = (const float*)d_in[1];
    const float* v    = (const float*)d_in[2];
    const int*   mask = (const int*)d_in[3];
    const float* Wq   = (const float*)d_in[4];
    const float* Wout = (const float*)d_in[5];
    float* out = (float*)d_out;

    const int attn_smem = 3 * 64 * LDA * (int)sizeof(float);  // 52224 bytes
    cudaFuncSetAttribute(attn_kernel, cudaFuncAttributeMaxDynamicSharedMemorySize,
                         attn_smem);
    cudaFuncSetAttribute(proj_mm, cudaFuncAttributeMaxDynamicSharedMemorySize,
                         MMSMEM);
    cudaFuncSetAttribute(out_mm, cudaFuncAttributeMaxDynamicSharedMemorySize,
                         MMSMEM);

    // 1) fp32 -> bf16 hi/lo conversions
    conv_kernel<<<4096, 256>>>((const float4*)q,    0, 1048576);
    conv_kernel<<<4096, 256>>>((const float4*)k,    1, 1048576);
    conv_kernel<<<4096, 256>>>((const float4*)v,    2, 1048576);
    conv_kernel<<<1024, 256>>>((const float4*)Wq,   3, 262144);
    conv_kernel<<<1024, 256>>>((const float4*)Wout, 4, 262144);

    // 2) Q/K/V projections (all use Wq, faithful to the reference)
    proj_mm<<<dim3(8, 32, 3), 512, MMSMEM>>>();

    // 3) Flash attention with ALiBi (writes ctx as bf16 hi/lo)
    attn_kernel<<<dim3(16, 64), 256, attn_smem>>>(mask);

    // 4) Output projection
    out_mm<<<dim3(8, 32), 512, MMSMEM>>>(out);
}

// round 13
// speedup vs baseline: 2.7727x; 1.4730x over previous
#include <cuda_runtime.h>
#include <cuda_bf16.h>
#include <math.h>

// Problem constants (fixed by the reference)
#define BB 4
#define SS 1024
#define DD 1024
#define HH 16
#define HD 64

// ---------------------------------------------------------------------------
// Device scratch (allocation-free rule: __device__ globals)
// ---------------------------------------------------------------------------
// bf16 hi/lo split inputs for projection GEMMs
__device__ __nv_bfloat16 g_xh[3*4096*1024];   // q,k,v hi
__device__ __nv_bfloat16 g_xl[3*4096*1024];   // q,k,v lo
__device__ __nv_bfloat16 g_wqh[1024*1024];
__device__ __nv_bfloat16 g_wql[1024*1024];
__device__ __nv_bfloat16 g_woh[1024*1024];
__device__ __nv_bfloat16 g_wol[1024*1024];

// Projected tensors, bf16 hi/lo (written by proj_mm epilogue)
__device__ __nv_bfloat16 g_Qh[4096*1024];     // [bh][s][64] row-major
__device__ __nv_bfloat16 g_Ql[4096*1024];
__device__ __nv_bfloat16 g_Kh[4096*1024];     // [bh][s][64] row-major
__device__ __nv_bfloat16 g_Kl[4096*1024];
__device__ __nv_bfloat16 g_Vth[4096*1024];    // [bh][d][s] TRANSPOSED
__device__ __nv_bfloat16 g_Vtl[4096*1024];

// Attention output, bf16 hi/lo [B,S,D]
__device__ __nv_bfloat16 g_ctxh[4096*1024];
__device__ __nv_bfloat16 g_ctxl[4096*1024];

// ---------------------------------------------------------------------------
// Helpers
// ---------------------------------------------------------------------------
__device__ __forceinline__ unsigned smem_u32(const void* p) {
    unsigned a;
    asm("{ .reg .u64 t; cvta.to.shared.u64 t, %1; cvt.u32.u64 %0, t; }"
        : "=r"(a) : "l"(p));
    return a;
}

__device__ __forceinline__ void cp16(unsigned saddr, const void* gaddr) {
    asm volatile("cp.async.cg.shared.global [%0], [%1], 16;"
                 :: "r"(saddr), "l"(gaddr));
}
#define CP_COMMIT() asm volatile("cp.async.commit_group;" ::: "memory")
#define CP_WAIT0()  asm volatile("cp.async.wait_group 0;" ::: "memory")

// bf16 MMA m16n8k16, fp32 accumulate (legacy tensor path; compiles for sm_103)
__device__ __forceinline__ void mma16(float c[4], const unsigned a[4],
                                      const unsigned b[2]) {
    asm volatile(
        "mma.sync.aligned.m16n8k16.row.col.f32.bf16.bf16.f32 "
        "{%0,%1,%2,%3},{%4,%5,%6,%7},{%8,%9},{%0,%1,%2,%3};"
        : "+f"(c[0]), "+f"(c[1]), "+f"(c[2]), "+f"(c[3])
        : "r"(a[0]), "r"(a[1]), "r"(a[2]), "r"(a[3]), "r"(b[0]), "r"(b[1]));
}

// fp32 pair -> packed bf16 hi pair + lo pair
__device__ __forceinline__ void cvt_hilo2(float x, float y,
                                          unsigned& hp, unsigned& lp) {
    __nv_bfloat16 hx = __float2bfloat16_rn(x);
    __nv_bfloat16 hy = __float2bfloat16_rn(y);
    __nv_bfloat16 lx = __float2bfloat16_rn(x - __bfloat162float(hx));
    __nv_bfloat16 ly = __float2bfloat16_rn(y - __bfloat162float(hy));
    hp = (unsigned)*(unsigned short*)&hx | ((unsigned)*(unsigned short*)&hy << 16);
    lp = (unsigned)*(unsigned short*)&lx | ((unsigned)*(unsigned short*)&ly << 16);
}

// ---------------------------------------------------------------------------
// bf16 hi/lo split GEMM: Y = A @ B^T  (M x 1024) @ (1024 x 1024)^T
// Block 128x128, BK=32, 512 threads, cp.async double-buffered, 3 MMA passes.
// MODE 0: bf16 hi/lo head-scatter [bh][s][64];  MODE 1: fp32 row-major;
// MODE 2: bf16 hi/lo transposed per head [bh][d][s].
// ---------------------------------------------------------------------------
#define LDH 40                      // bf16 halves per smem row (32 + 8 pad)
#define LDW 20                      // 32-bit words per smem row
#define MATB (128*LDH*2)            // 10240 bytes per matrix tile
#define STAGEB (4*MATB)             // Ah,Al,Bh,Bl = 40960 bytes per stage
#define MMSMEM (2*STAGEB)           // 81920 bytes

template<int MODE>
__device__ __forceinline__ void mm_body(const __nv_bfloat16* __restrict__ Ahp,
                                        const __nv_bfloat16* __restrict__ Alp,
                                        const __nv_bfloat16* __restrict__ Bhp,
                                        const __nv_bfloat16* __restrict__ Blp,
                                        float* __restrict__ Y,
                                        __nv_bfloat16* __restrict__ Yh,
                                        __nv_bfloat16* __restrict__ Yl)
{
    extern __shared__ char smc[];
    const unsigned sb = smem_u32(smc);
    const int tid = threadIdx.x;
    const int lane = tid & 31, warp = tid >> 5;
    const int g = lane >> 2, c = lane & 3;
    const int wm = warp >> 2, wn = warp & 3;
    const int m0 = blockIdx.y * 128, n0 = blockIdx.x * 128;

    float acc[2][4][4];
    #pragma unroll
    for (int mi = 0; mi < 2; mi++)
        #pragma unroll
        for (int ni = 0; ni < 4; ni++)
            #pragma unroll
            for (int r = 0; r < 4; r++) acc[mi][ni][r] = 0.f;

    const int mat = tid >> 7;         // 0=Ah 1=Al 2=Bh 3=Bl
    const int t = tid & 127;
    const __nv_bfloat16* gp = (mat == 0) ? Ahp : (mat == 1) ? Alp
                            : (mat == 2) ? Bhp : Blp;
    const int rowoff = (mat >= 2) ? n0 : m0;
    const unsigned smat = (unsigned)(mat * MATB);

    auto stage = [&](int kc, int buf) {
        #pragma unroll
        for (int i = 0; i < 4; i++) {
            int id = t + i * 128;
            int row = id >> 2, seg = id & 3;
            const void* ga = gp + (size_t)(rowoff + row) * 1024 + kc * 32 + seg * 8;
            unsigned sa = sb + (unsigned)buf * STAGEB + smat
                        + (unsigned)(row * (LDH * 2) + seg * 16);
            cp16(sa, ga);
        }
        CP_COMMIT();
    };

    stage(0, 0);

    for (int kc = 0; kc < 32; kc++) {
        CP_WAIT0();
        __syncthreads();
        if (kc + 1 < 32) stage(kc + 1, (kc + 1) & 1);

        const unsigned* Ahw = (const unsigned*)(smc + (size_t)(kc & 1) * STAGEB);
        const unsigned* Alw = Ahw + MATB / 4;
        const unsigned* Bhw = Ahw + 2 * (MATB / 4);
        const unsigned* Blw = Ahw + 3 * (MATB / 4);

        #pragma unroll
        for (int ks = 0; ks < 2; ks++) {
            unsigned ah[2][4], al[2][4];
            #pragma unroll
            for (int mi = 0; mi < 2; mi++) {
                int rb = wm * 32 + mi * 16;
                int w0 = (rb + g) * LDW + ks * 8 + c;
                int w1 = (rb + 8 + g) * LDW + ks * 8 + c;
                ah[mi][0] = Ahw[w0];     ah[mi][1] = Ahw[w1];
                ah[mi][2] = Ahw[w0 + 4]; ah[mi][3] = Ahw[w1 + 4];
                al[mi][0] = Alw[w0];     al[mi][1] = Alw[w1];
                al[mi][2] = Alw[w0 + 4]; al[mi][3] = Alw[w1 + 4];
            }
            unsigned bh[4][2], bl[4][2];
            #pragma unroll
            for (int ni = 0; ni < 4; ni++) {
                int nr = wn * 32 + ni * 8 + g;
                int w = nr * LDW + ks * 8 + c;
                bh[ni][0] = Bhw[w]; bh[ni][1] = Bhw[w + 4];
                bl[ni][0] = Blw[w]; bl[ni][1] = Blw[w + 4];
            }
            #pragma unroll
            for (int mi = 0; mi < 2; mi++)
                #pragma unroll
                for (int ni = 0; ni < 4; ni++) {
                    mma16(acc[mi][ni], ah[mi], bh[ni]);
                    mma16(acc[mi][ni], ah[mi], bl[ni]);
                    mma16(acc[mi][ni], al[mi], bh[ni]);
                }
        }
    }

    // Epilogue. C frag: c0,c1=(g,2c),(g,2c+1); c2,c3=(g+8,2c),(g+8,2c+1)
    #pragma unroll
    for (int mi = 0; mi < 2; mi++) {
        #pragma unroll
        for (int half = 0; half < 2; half++) {
            int m = m0 + wm * 32 + mi * 16 + g + half * 8;
            #pragma unroll
            for (int ni = 0; ni < 4; ni++) {
                int n = n0 + wn * 32 + ni * 8 + c * 2;
                float vx = acc[mi][ni][half * 2];
                float vy = acc[mi][ni][half * 2 + 1];
                if (MODE == 1) {
                    float2 val; val.x = vx; val.y = vy;
                    *(float2*)&Y[(size_t)m * 1024 + n] = val;
                } else {
                    int b = m >> 10, s = m & 1023, h = n >> 6, d = n & 63;
                    unsigned hp, lp;
                    cvt_hilo2(vx, vy, hp, lp);
                    if (MODE == 0) {
                        size_t a = (((size_t)(b * HH + h)) * SS + s) * HD + d;
                        *(unsigned*)&Yh[a] = hp;
                        *(unsigned*)&Yl[a] = lp;
                    } else {   // MODE 2: transposed per head [bh][d][s]
                        size_t a = (((size_t)(b * HH + h)) * HD + d) * SS + s;
                        Yh[a]      = *(__nv_bfloat16*)&hp;
                        Yl[a]      = *(__nv_bfloat16*)&lp;
                        unsigned hp2 = hp >> 16, lp2 = lp >> 16;
                        Yh[a + SS] = *(__nv_bfloat16*)&hp2;
                        Yl[a + SS] = *(__nv_bfloat16*)&lp2;
                    }
                }
            }
        }
    }
}

__global__ __launch_bounds__(512, 1) void proj_mm()
{
    int z = blockIdx.z;
    const __nv_bfloat16* xh = g_xh + (size_t)z * 4194304;
    const __nv_bfloat16* xl = g_xl + (size_t)z * 4194304;
    if (z == 0)      mm_body<0>(xh, xl, g_wqh, g_wql, nullptr, g_Qh, g_Ql);
    else if (z == 1) mm_body<0>(xh, xl, g_wqh, g_wql, nullptr, g_Kh, g_Kl);
    else             mm_body<2>(xh, xl, g_wqh, g_wql, nullptr, g_Vth, g_Vtl);
}

__global__ __launch_bounds__(512, 1) void out_mm(float* __restrict__ out)
{
    mm_body<1>(g_ctxh, g_ctxl, g_woh, g_wol, out, nullptr, nullptr);
}

// ---------------------------------------------------------------------------
// fp32 -> bf16 hi/lo conversion (one float4 per thread)
// ---------------------------------------------------------------------------
__global__ __launch_bounds__(256) void conv_kernel(const float4* __restrict__ src,
                                                   int sel, int n4)
{
    int idx = blockIdx.x * 256 + threadIdx.x;
    if (idx >= n4) return;
    __nv_bfloat16 *hi, *lo;
    if (sel < 3)      { hi = g_xh + (size_t)sel * 4194304; lo = g_xl + (size_t)sel * 4194304; }
    else if (sel == 3){ hi = g_wqh; lo = g_wql; }
    else              { hi = g_woh; lo = g_wol; }
    float4 f = src[idx];
    uint2 H, L;
    cvt_hilo2(f.x, f.y, H.x, L.x);
    cvt_hilo2(f.z, f.w, H.y, L.y);
    ((uint2*)hi)[idx] = H;
    ((uint2*)lo)[idx] = L;
}

// ---------------------------------------------------------------------------
// Tensor-core flash attention with ALiBi.
// Block: 128 q rows x one (b,h).  8 warps, warp tile 16q x 64k, m16n8k16.
// 3-pass hi/lo for both QK^T and PV. K/V tiles cp.async double-buffered.
// Smem rows padded to 72 bf16 (36 words): frag reads conflict-free (4g+c).
// ---------------------------------------------------------------------------
#define AT_MAT   9216                // 64 rows * 144 bytes
#define AT_STAGE (4*AT_MAT)          // Kh,Kl,Vth,Vtl
#define AT_SMEM  (2*AT_STAGE)        // 73728 bytes

__global__ __launch_bounds__(256, 1) void attn_kernel(const int* __restrict__ mask)
{
    extern __shared__ char smc[];
    __shared__ float mneg[1024];
    const unsigned sb = smem_u32(smc);
    const int tid = threadIdx.x;
    const int lane = tid & 31, wq = tid >> 5;
    const int g = lane >> 2, c = lane & 3;
    const int bh = blockIdx.y, b = bh >> 4, h = bh & 15;
    const int q0 = blockIdx.x * 128;
    const float slope = exp2f(-0.5f * (float)(h + 1));

    // Mask table for this batch row (once per block)
    #pragma unroll
    for (int i = 0; i < 4; i++) {
        int j = tid + i * 256;
        mneg[j] = (mask[b * SS + j] == 0) ? -1e9f : 0.f;
    }

    // Q fragments (held in registers for the whole block)
    const unsigned* qwh = (const unsigned*)(g_Qh + (size_t)bh * 65536
                                            + (size_t)(q0 + wq * 16) * 64);
    const unsigned* qwl = (const unsigned*)(g_Ql + (size_t)bh * 65536
                                            + (size_t)(q0 + wq * 16) * 64);
    unsigned qh[4][4], ql[4][4];
    #pragma unroll
    for (int ks = 0; ks < 4; ks++) {
        int w0 = g * 32 + ks * 8 + c, w1 = (g + 8) * 32 + ks * 8 + c;
        qh[ks][0] = qwh[w0];     qh[ks][1] = qwh[w1];
        qh[ks][2] = qwh[w0 + 4]; qh[ks][3] = qwh[w1 + 4];
        ql[ks][0] = qwl[w0];     ql[ks][1] = qwl[w1];
        ql[ks][2] = qwl[w0 + 4]; ql[ks][3] = qwl[w1 + 4];
    }

    const __nv_bfloat16* Kh = g_Kh + (size_t)bh * 65536;
    const __nv_bfloat16* Kl = g_Kl + (size_t)bh * 65536;
    const __nv_bfloat16* Vh = g_Vth + (size_t)bh * 65536;
    const __nv_bfloat16* Vl = g_Vtl + (size_t)bh * 65536;

    auto stage = [&](int kt, int buf) {
        int kb = kt * 64;
        #pragma unroll
        for (int i = 0; i < 2; i++) {
            int id = tid + i * 256;          // 0..511
            int row = id >> 3, slot = id & 7;
            unsigned dst = sb + (unsigned)buf * AT_STAGE
                         + (unsigned)(row * 144 + slot * 16);
            cp16(dst,              Kh + (size_t)(kb + row) * 64 + slot * 8);
            cp16(dst + AT_MAT,     Kl + (size_t)(kb + row) * 64 + slot * 8);
            cp16(dst + 2*AT_MAT,   Vh + (size_t)row * 1024 + kb + slot * 8);
            cp16(dst + 3*AT_MAT,   Vl + (size_t)row * 1024 + kb + slot * 8);
        }
        CP_COMMIT();
    };

    float oc[8][4];
    #pragma unroll
    for (int nt = 0; nt < 8; nt++)
        #pragma unroll
        for (int r = 0; r < 4; r++) oc[nt][r] = 0.f;
    float m0r = -1e30f, m1r = -1e30f, l0r = 0.f, l1r = 0.f;
    const int qi0 = q0 + wq * 16 + g, qi1 = qi0 + 8;

    stage(0, 0);

    #pragma unroll 1
    for (int kt = 0; kt < 16; kt++) {
        CP_WAIT0();
        __syncthreads();
        if (kt < 15) stage(kt + 1, (kt + 1) & 1);

        const unsigned* Khw = (const unsigned*)(smc + (size_t)(kt & 1) * AT_STAGE);
        const unsigned* Klw = Khw + AT_MAT / 4;
        const unsigned* Vhw = Khw + 2 * (AT_MAT / 4);
        const unsigned* Vlw = Khw + 3 * (AT_MAT / 4);

        // S = Q K^T (3-pass hi/lo)
        float sc[8][4];
        #pragma unroll
        for (int nt = 0; nt < 8; nt++)
            #pragma unroll
            for (int r = 0; r < 4; r++) sc[nt][r] = 0.f;

        #pragma unroll
        for (int ks = 0; ks < 4; ks++) {
            #pragma unroll
            for (int nt = 0; nt < 8; nt++) {
                int w = (nt * 8 + g) * 36 + ks * 8 + c;
                unsigned kbh[2] = { Khw[w], Khw[w + 4] };
                unsigned kbl[2] = { Klw[w], Klw[w + 4] };
                mma16(sc[nt], qh[ks], kbh);
                mma16(sc[nt], qh[ks], kbl);
                mma16(sc[nt], ql[ks], kbh);
            }
        }

        // ALiBi bias + mask
        int kb = kt * 64;
        #pragma unroll
        for (int nt = 0; nt < 8; nt++) {
            int kj = kb + nt * 8 + 2 * c;
            float mn0 = mneg[kj], mn1 = mneg[kj + 1];
            float b00 = slope * fminf((float)(kj     - qi0), 0.f);
            float b10 = slope * fminf((float)(kj + 1 - qi0), 0.f);
            float b01 = slope * fminf((float)(kj     - qi1), 0.f);
            float b11 = slope * fminf((float)(kj + 1 - qi1), 0.f);
            sc[nt][0] = (mn0 != 0.f) ? -1e9f : sc[nt][0] + b00;
            sc[nt][1] = (mn1 != 0.f) ? -1e9f : sc[nt][1] + b10;
            sc[nt][2] = (mn0 != 0.f) ? -1e9f : sc[nt][2] + b01;
            sc[nt][3] = (mn1 != 0.f) ? -1e9f : sc[nt][3] + b11;
        }

        // Online softmax (rows g and g+8; each row lives in a 4-lane quad)
        float mt0 = -1e30f, mt1 = -1e30f;
        #pragma unroll
        for (int nt = 0; nt < 8; nt++) {
            mt0 = fmaxf(mt0, fmaxf(sc[nt][0], sc[nt][1]));
            mt1 = fmaxf(mt1, fmaxf(sc[nt][2], sc[nt][3]));
        }
        mt0 = fmaxf(mt0, __shfl_xor_sync(0xffffffffu, mt0, 1));
        mt0 = fmaxf(mt0, __shfl_xor_sync(0xffffffffu, mt0, 2));
        mt1 = fmaxf(mt1, __shfl_xor_sync(0xffffffffu, mt1, 1));
        mt1 = fmaxf(mt1, __shfl_xor_sync(0xffffffffu, mt1, 2));
        float nm0 = fmaxf(m0r, mt0), nm1 = fmaxf(m1r, mt1);
        float corr0 = __expf(m0r - nm0), corr1 = __expf(m1r - nm1);
        float rs0 = 0.f, rs1 = 0.f;
        #pragma unroll
        for (int nt = 0; nt < 8; nt++) {
            sc[nt][0] = __expf(sc[nt][0] - nm0);
            sc[nt][1] = __expf(sc[nt][1] - nm0);
            sc[nt][2] = __expf(sc[nt][2] - nm1);
            sc[nt][3] = __expf(sc[nt][3] - nm1);
            rs0 += sc[nt][0] + sc[nt][1];
            rs1 += sc[nt][2] + sc[nt][3];
        }
        rs0 += __shfl_xor_sync(0xffffffffu, rs0, 1);
        rs0 += __shfl_xor_sync(0xffffffffu, rs0, 2);
        rs1 += __shfl_xor_sync(0xffffffffu, rs1, 1);
        rs1 += __shfl_xor_sync(0xffffffffu, rs1, 2);
        l0r = l0r * corr0 + rs0;  m0r = nm0;
        l1r = l1r * corr1 + rs1;  m1r = nm1;
        #pragma unroll
        for (int nt = 0; nt < 8; nt++) {
            oc[nt][0] *= corr0; oc[nt][1] *= corr0;
            oc[nt][2] *= corr1; oc[nt][3] *= corr1;
        }

        // O += P V  (P repacked from C-frags in registers; 3-pass hi/lo)
        #pragma unroll
        for (int ks = 0; ks < 4; ks++) {
            unsigned pah[4], pal[4];
            cvt_hilo2(sc[2*ks][0],   sc[2*ks][1],   pah[0], pal[0]);
            cvt_hilo2(sc[2*ks][2],   sc[2*ks][3],   pah[1], pal[1]);
            cvt_hilo2(sc[2*ks+1][0], sc[2*ks+1][1], pah[2], pal[2]);
            cvt_hilo2(sc[2*ks+1][2], sc[2*ks+1][3], pah[3], pal[3]);
            #pragma unroll
            for (int nt = 0; nt < 8; nt++) {
                int w = (nt * 8 + g) * 36 + ks * 8 + c;
                unsigned vbh[2] = { Vhw[w], Vhw[w + 4] };
                unsigned vbl[2] = { Vlw[w], Vlw[w + 4] };
                mma16(oc[nt], pah, vbh);
                mma16(oc[nt], pah, vbl);
                mma16(oc[nt], pal, vbh);
            }
        }
    }

    // Epilogue: normalize, write ctx bf16 hi/lo at [b][s][h*64+d]
    float inv0 = 1.f / l0r, inv1 = 1.f / l1r;
    size_t base0 = ((size_t)b * SS + qi0) * DD + h * HD;
    size_t base1 = ((size_t)b * SS + qi1) * DD + h * HD;
    #pragma unroll
    for (int nt = 0; nt < 8; nt++) {
        int d = nt * 8 + 2 * c;
        unsigned hp, lp;
        cvt_hilo2(oc[nt][0] * inv0, oc[nt][1] * inv0, hp, lp);
        *(unsigned*)&g_ctxh[base0 + d] = hp;
        *(unsigned*)&g_ctxl[base0 + d] = lp;
        cvt_hilo2(oc[nt][2] * inv1, oc[nt][3] * inv1, hp, lp);
        *(unsigned*)&g_ctxh[base1 + d] = hp;
        *(unsigned*)&g_ctxl[base1 + d] = lp;
    }
}

// ---------------------------------------------------------------------------
extern "C" void kernel_launch(void* const* d_in, const int* in_sizes, int n_in,
                              void* d_out, int out_size)
{
    const float* q    = (const float*)d_in[0];
    const float* k    = (const float*)d_in[1];
    const float* v    = (const float*)d_in[2];
    const int*   mask = (const int*)d_in[3];
    const float* Wq   = (const float*)d_in[4];
    const float* Wout = (const float*)d_in[5];
    float* out = (float*)d_out;

    cudaFuncSetAttribute(attn_kernel, cudaFuncAttributeMaxDynamicSharedMemorySize,
                         AT_SMEM);
    cudaFuncSetAttribute(proj_mm, cudaFuncAttributeMaxDynamicSharedMemorySize,
                         MMSMEM);
    cudaFuncSetAttribute(out_mm, cudaFuncAttributeMaxDynamicSharedMemorySize,
                         MMSMEM);

    // 1) fp32 -> bf16 hi/lo conversions
    conv_kernel<<<4096, 256>>>((const float4*)q,    0, 1048576);
    conv_kernel<<<4096, 256>>>((const float4*)k,    1, 1048576);
    conv_kernel<<<4096, 256>>>((const float4*)v,    2, 1048576);
    conv_kernel<<<1024, 256>>>((const float4*)Wq,   3, 262144);
    conv_kernel<<<1024, 256>>>((const float4*)Wout, 4, 262144);

    // 2) Q/K/V projections (all use Wq, faithful to the reference);
    //    emits bf16 hi/lo Q,K row-major and V transposed.
    proj_mm<<<dim3(8, 32, 3), 512, MMSMEM>>>();

    // 3) Tensor-core flash attention with ALiBi (writes ctx bf16 hi/lo)
    attn_kernel<<<dim3(8, 64), 256, AT_SMEM>>>(mask);

    // 4) Output projection
    out_mm<<<dim3(8, 32), 512, MMSMEM>>>(out);
}

// round 14
// speedup vs baseline: 2.7908x; 1.0065x over previous
#include <cuda_runtime.h>
#include <cuda_bf16.h>
#include <math.h>

// Problem constants (fixed by the reference)
#define BB 4
#define SS 1024
#define DD 1024
#define HH 16
#define HD 64

// ---------------------------------------------------------------------------
// Device scratch (allocation-free rule: __device__ globals)
// ---------------------------------------------------------------------------
__device__ __nv_bfloat16 g_xh[3*4096*1024];   // q,k,v hi
__device__ __nv_bfloat16 g_xl[3*4096*1024];   // q,k,v lo
__device__ __nv_bfloat16 g_wqh[1024*1024];
__device__ __nv_bfloat16 g_wql[1024*1024];
__device__ __nv_bfloat16 g_woh[1024*1024];
__device__ __nv_bfloat16 g_wol[1024*1024];

__device__ __nv_bfloat16 g_Qh[4096*1024];     // [bh][s][64] row-major
__device__ __nv_bfloat16 g_Ql[4096*1024];
__device__ __nv_bfloat16 g_Kh[4096*1024];     // [bh][s][64] row-major
__device__ __nv_bfloat16 g_Kl[4096*1024];
__device__ __nv_bfloat16 g_Vth[4096*1024];    // [bh][d][s] TRANSPOSED
__device__ __nv_bfloat16 g_Vtl[4096*1024];

__device__ __nv_bfloat16 g_ctxh[4096*1024];   // attention output [B,S,D]
__device__ __nv_bfloat16 g_ctxl[4096*1024];

// ---------------------------------------------------------------------------
// Helpers
// ---------------------------------------------------------------------------
__device__ __forceinline__ unsigned smem_u32(const void* p) {
    unsigned a;
    asm("{ .reg .u64 t; cvta.to.shared.u64 t, %1; cvt.u32.u64 %0, t; }"
        : "=r"(a) : "l"(p));
    return a;
}

__device__ __forceinline__ void cp16(unsigned saddr, const void* gaddr) {
    asm volatile("cp.async.cg.shared.global [%0], [%1], 16;"
                 :: "r"(saddr), "l"(gaddr));
}
#define CP_COMMIT() asm volatile("cp.async.commit_group;" ::: "memory")
#define CP_WAIT0()  asm volatile("cp.async.wait_group 0;" ::: "memory")

__device__ __forceinline__ void mma16(float c[4], const unsigned a[4],
                                      const unsigned b[2]) {
    asm volatile(
        "mma.sync.aligned.m16n8k16.row.col.f32.bf16.bf16.f32 "
        "{%0,%1,%2,%3},{%4,%5,%6,%7},{%8,%9},{%0,%1,%2,%3};"
        : "+f"(c[0]), "+f"(c[1]), "+f"(c[2]), "+f"(c[3])
        : "r"(a[0]), "r"(a[1]), "r"(a[2]), "r"(a[3]), "r"(b[0]), "r"(b[1]));
}

__device__ __forceinline__ void cvt_hilo2(float x, float y,
                                          unsigned& hp, unsigned& lp) {
    __nv_bfloat16 hx = __float2bfloat16_rn(x);
    __nv_bfloat16 hy = __float2bfloat16_rn(y);
    __nv_bfloat16 lx = __float2bfloat16_rn(x - __bfloat162float(hx));
    __nv_bfloat16 ly = __float2bfloat16_rn(y - __bfloat162float(hy));
    hp = (unsigned)*(unsigned short*)&hx | ((unsigned)*(unsigned short*)&hy << 16);
    lp = (unsigned)*(unsigned short*)&lx | ((unsigned)*(unsigned short*)&ly << 16);
}

// ---------------------------------------------------------------------------
// bf16 hi/lo split GEMM (unchanged from R13; ~410 TF/s effective)
// ---------------------------------------------------------------------------
#define LDH 40
#define LDW 20
#define MATB (128*LDH*2)
#define STAGEB (4*MATB)
#define MMSMEM (2*STAGEB)

template<int MODE>
__device__ __forceinline__ void mm_body(const __nv_bfloat16* __restrict__ Ahp,
                                        const __nv_bfloat16* __restrict__ Alp,
                                        const __nv_bfloat16* __restrict__ Bhp,
                                        const __nv_bfloat16* __restrict__ Blp,
                                        float* __restrict__ Y,
                                        __nv_bfloat16* __restrict__ Yh,
                                        __nv_bfloat16* __restrict__ Yl)
{
    extern __shared__ char smc[];
    const unsigned sb = smem_u32(smc);
    const int tid = threadIdx.x;
    const int lane = tid & 31, warp = tid >> 5;
    const int g = lane >> 2, c = lane & 3;
    const int wm = warp >> 2, wn = warp & 3;
    const int m0 = blockIdx.y * 128, n0 = blockIdx.x * 128;

    float acc[2][4][4];
    #pragma unroll
    for (int mi = 0; mi < 2; mi++)
        #pragma unroll
        for (int ni = 0; ni < 4; ni++)
            #pragma unroll
            for (int r = 0; r < 4; r++) acc[mi][ni][r] = 0.f;

    const int mat = tid >> 7;
    const int t = tid & 127;
    const __nv_bfloat16* gp = (mat == 0) ? Ahp : (mat == 1) ? Alp
                            : (mat == 2) ? Bhp : Blp;
    const int rowoff = (mat >= 2) ? n0 : m0;
    const unsigned smat = (unsigned)(mat * MATB);

    auto stage = [&](int kc, int buf) {
        #pragma unroll
        for (int i = 0; i < 4; i++) {
            int id = t + i * 128;
            int row = id >> 2, seg = id & 3;
            const void* ga = gp + (size_t)(rowoff + row) * 1024 + kc * 32 + seg * 8;
            unsigned sa = sb + (unsigned)buf * STAGEB + smat
                        + (unsigned)(row * (LDH * 2) + seg * 16);
            cp16(sa, ga);
        }
        CP_COMMIT();
    };

    stage(0, 0);

    for (int kc = 0; kc < 32; kc++) {
        CP_WAIT0();
        __syncthreads();
        if (kc + 1 < 32) stage(kc + 1, (kc + 1) & 1);

        const unsigned* Ahw = (const unsigned*)(smc + (size_t)(kc & 1) * STAGEB);
        const unsigned* Alw = Ahw + MATB / 4;
        const unsigned* Bhw = Ahw + 2 * (MATB / 4);
        const unsigned* Blw = Ahw + 3 * (MATB / 4);

        #pragma unroll
        for (int ks = 0; ks < 2; ks++) {
            unsigned ah[2][4], al[2][4];
            #pragma unroll
            for (int mi = 0; mi < 2; mi++) {
                int rb = wm * 32 + mi * 16;
                int w0 = (rb + g) * LDW + ks * 8 + c;
                int w1 = (rb + 8 + g) * LDW + ks * 8 + c;
                ah[mi][0] = Ahw[w0];     ah[mi][1] = Ahw[w1];
                ah[mi][2] = Ahw[w0 + 4]; ah[mi][3] = Ahw[w1 + 4];
                al[mi][0] = Alw[w0];     al[mi][1] = Alw[w1];
                al[mi][2] = Alw[w0 + 4]; al[mi][3] = Alw[w1 + 4];
            }
            unsigned bh[4][2], bl[4][2];
            #pragma unroll
            for (int ni = 0; ni < 4; ni++) {
                int nr = wn * 32 + ni * 8 + g;
                int w = nr * LDW + ks * 8 + c;
                bh[ni][0] = Bhw[w]; bh[ni][1] = Bhw[w + 4];
                bl[ni][0] = Blw[w]; bl[ni][1] = Blw[w + 4];
            }
            #pragma unroll
            for (int mi = 0; mi < 2; mi++)
                #pragma unroll
                for (int ni = 0; ni < 4; ni++) {
                    mma16(acc[mi][ni], ah[mi], bh[ni]);
                    mma16(acc[mi][ni], ah[mi], bl[ni]);
                    mma16(acc[mi][ni], al[mi], bh[ni]);
                }
        }
    }

    #pragma unroll
    for (int mi = 0; mi < 2; mi++) {
        #pragma unroll
        for (int half = 0; half < 2; half++) {
            int m = m0 + wm * 32 + mi * 16 + g + half * 8;
            #pragma unroll
            for (int ni = 0; ni < 4; ni++) {
                int n = n0 + wn * 32 + ni * 8 + c * 2;
                float vx = acc[mi][ni][half * 2];
                float vy = acc[mi][ni][half * 2 + 1];
                if (MODE == 1) {
                    float2 val; val.x = vx; val.y = vy;
                    *(float2*)&Y[(size_t)m * 1024 + n] = val;
                } else {
                    int b = m >> 10, s = m & 1023, h = n >> 6, d = n & 63;
                    unsigned hp, lp;
                    cvt_hilo2(vx, vy, hp, lp);
                    if (MODE == 0) {
                        size_t a = (((size_t)(b * HH + h)) * SS + s) * HD + d;
                        *(unsigned*)&Yh[a] = hp;
                        *(unsigned*)&Yl[a] = lp;
                    } else {   // MODE 2: transposed per head [bh][d][s]
                        size_t a = (((size_t)(b * HH + h)) * HD + d) * SS + s;
                        Yh[a]      = *(__nv_bfloat16*)&hp;
                        Yl[a]      = *(__nv_bfloat16*)&lp;
                        unsigned hp2 = hp >> 16, lp2 = lp >> 16;
                        Yh[a + SS] = *(__nv_bfloat16*)&hp2;
                        Yl[a + SS] = *(__nv_bfloat16*)&lp2;
                    }
                }
            }
        }
    }
}

__global__ __launch_bounds__(512, 1) void proj_mm()
{
    int z = blockIdx.z;
    const __nv_bfloat16* xh = g_xh + (size_t)z * 4194304;
    const __nv_bfloat16* xl = g_xl + (size_t)z * 4194304;
    if (z == 0)      mm_body<0>(xh, xl, g_wqh, g_wql, nullptr, g_Qh, g_Ql);
    else if (z == 1) mm_body<0>(xh, xl, g_wqh, g_wql, nullptr, g_Kh, g_Kl);
    else             mm_body<2>(xh, xl, g_wqh, g_wql, nullptr, g_Vth, g_Vtl);
}

__global__ __launch_bounds__(512, 1) void out_mm(float* __restrict__ out)
{
    mm_body<1>(g_ctxh, g_ctxl, g_woh, g_wol, out, nullptr, nullptr);
}

// ---------------------------------------------------------------------------
// fp32 -> bf16 hi/lo conversion, z-batched (z picks tensor)
// ---------------------------------------------------------------------------
__global__ __launch_bounds__(256) void conv_x(const float4* __restrict__ q,
                                              const float4* __restrict__ k,
                                              const float4* __restrict__ v)
{
    int z = blockIdx.z;
    const float4* src = (z == 0) ? q : (z == 1) ? k : v;
    int idx = blockIdx.x * 256 + threadIdx.x;
    __nv_bfloat16* hi = g_xh + (size_t)z * 4194304;
    __nv_bfloat16* lo = g_xl + (size_t)z * 4194304;
    float4 f = src[idx];
    uint2 H, L;
    cvt_hilo2(f.x, f.y, H.x, L.x);
    cvt_hilo2(f.z, f.w, H.y, L.y);
    ((uint2*)hi)[idx] = H;
    ((uint2*)lo)[idx] = L;
}

__global__ __launch_bounds__(256) void conv_w(const float4* __restrict__ wq,
                                              const float4* __restrict__ wo)
{
    int z = blockIdx.z;
    const float4* src = (z == 0) ? wq : wo;
    int idx = blockIdx.x * 256 + threadIdx.x;
    __nv_bfloat16* hi = (z == 0) ? g_wqh : g_woh;
    __nv_bfloat16* lo = (z == 0) ? g_wql : g_wol;
    float4 f = src[idx];
    uint2 H, L;
    cvt_hilo2(f.x, f.y, H.x, L.x);
    cvt_hilo2(f.z, f.w, H.y, L.y);
    ((uint2*)hi)[idx] = H;
    ((uint2*)lo)[idx] = L;
}

// ---------------------------------------------------------------------------
// Tensor-core flash attention with ALiBi.
// Block: 128 q rows x one (b,h). 8 warps, warp tile 16q x 32k, m16n8k16,
// 3-pass hi/lo both GEMMs. 32-key tiles, cp.async double-buffered,
// 2 CTAs/SM (smem 38.9KB dynamic, regs <= 128).
// ---------------------------------------------------------------------------
#define KMAT 4608                    // K tile: 32 keys * 144B (64d + pad)
#define VMAT 5120                    // V tile: 64 d * 80B (32k + pad)
#define AT_STAGE (2*KMAT + 2*VMAT)   // 19456
#define AT_SMEM  (2*AT_STAGE)        // 38912

__global__ __launch_bounds__(256, 2) void attn_kernel(const int* __restrict__ mask)
{
    extern __shared__ char smc[];
    __shared__ float mneg[1024];
    const unsigned sb = smem_u32(smc);
    const int tid = threadIdx.x;
    const int lane = tid & 31, wq = tid >> 5;
    const int g = lane >> 2, c = lane & 3;
    const int bh = blockIdx.y, b = bh >> 4, h = bh & 15;
    const int q0 = blockIdx.x * 128;
    const float slope = exp2f(-0.5f * (float)(h + 1));

    #pragma unroll
    for (int i = 0; i < 4; i++) {
        int j = tid + i * 256;
        mneg[j] = (mask[b * SS + j] == 0) ? -1e9f : 0.f;
    }

    // Q fragments (registers for whole block)
    const unsigned* qwh = (const unsigned*)(g_Qh + (size_t)bh * 65536
                                            + (size_t)(q0 + wq * 16) * 64);
    const unsigned* qwl = (const unsigned*)(g_Ql + (size_t)bh * 65536
                                            + (size_t)(q0 + wq * 16) * 64);
    unsigned qh[4][4], ql[4][4];
    #pragma unroll
    for (int ks = 0; ks < 4; ks++) {
        int w0 = g * 32 + ks * 8 + c, w1 = (g + 8) * 32 + ks * 8 + c;
        qh[ks][0] = qwh[w0];     qh[ks][1] = qwh[w1];
        qh[ks][2] = qwh[w0 + 4]; qh[ks][3] = qwh[w1 + 4];
        ql[ks][0] = qwl[w0];     ql[ks][1] = qwl[w1];
        ql[ks][2] = qwl[w0 + 4]; ql[ks][3] = qwl[w1 + 4];
    }

    const __nv_bfloat16* Kh = g_Kh + (size_t)bh * 65536;
    const __nv_bfloat16* Kl = g_Kl + (size_t)bh * 65536;
    const __nv_bfloat16* Vh = g_Vth + (size_t)bh * 65536;
    const __nv_bfloat16* Vl = g_Vtl + (size_t)bh * 65536;

    // Stage one 32-key tile: Kh/Kl rows=key (64d), Vh/Vl rows=d (32 keys).
    auto stage = [&](int kt, int buf) {
        int kb = kt * 32;
        unsigned s0 = sb + (unsigned)buf * AT_STAGE;
        {   // Kh: 256 cp16
            int row = tid >> 3, slot = tid & 7;
            cp16(s0 + (unsigned)(row * 144 + slot * 16),
                 Kh + (size_t)(kb + row) * 64 + slot * 8);
            cp16(s0 + KMAT + (unsigned)(row * 144 + slot * 16),
                 Kl + (size_t)(kb + row) * 64 + slot * 8);
        }
        {   // Vh/Vl: 256 cp16 each
            int row = tid >> 2, slot = tid & 3;
            cp16(s0 + 2*KMAT + (unsigned)(row * 80 + slot * 16),
                 Vh + (size_t)row * 1024 + kb + slot * 8);
            cp16(s0 + 2*KMAT + VMAT + (unsigned)(row * 80 + slot * 16),
                 Vl + (size_t)row * 1024 + kb + slot * 8);
        }
        CP_COMMIT();
    };

    float oc[8][4];
    #pragma unroll
    for (int nt = 0; nt < 8; nt++)
        #pragma unroll
        for (int r = 0; r < 4; r++) oc[nt][r] = 0.f;
    float m0r = -1e30f, m1r = -1e30f, l0r = 0.f, l1r = 0.f;
    const int qi0 = q0 + wq * 16 + g, qi1 = qi0 + 8;

    stage(0, 0);

    #pragma unroll 1
    for (int kt = 0; kt < 32; kt++) {
        CP_WAIT0();
        __syncthreads();
        if (kt < 31) stage(kt + 1, (kt + 1) & 1);

        const unsigned* Khw = (const unsigned*)(smc + (size_t)(kt & 1) * AT_STAGE);
        const unsigned* Klw = Khw + KMAT / 4;
        const unsigned* Vhw = Khw + 2 * (KMAT / 4);
        const unsigned* Vlw = Vhw + VMAT / 4;

        // S = Q K^T (3-pass hi/lo), 4 n-tiles of 8 keys
        float sc[4][4];
        #pragma unroll
        for (int nt = 0; nt < 4; nt++)
            #pragma unroll
            for (int r = 0; r < 4; r++) sc[nt][r] = 0.f;

        #pragma unroll
        for (int ks = 0; ks < 4; ks++) {
            #pragma unroll
            for (int nt = 0; nt < 4; nt++) {
                int w = (nt * 8 + g) * 36 + ks * 8 + c;
                unsigned kbh[2] = { Khw[w], Khw[w + 4] };
                unsigned kbl[2] = { Klw[w], Klw[w + 4] };
                mma16(sc[nt], qh[ks], kbh);
                mma16(sc[nt], qh[ks], kbl);
                mma16(sc[nt], ql[ks], kbh);
            }
        }

        // ALiBi bias + mask
        int kb = kt * 32;
        #pragma unroll
        for (int nt = 0; nt < 4; nt++) {
            int kj = kb + nt * 8 + 2 * c;
            float mn0 = mneg[kj], mn1 = mneg[kj + 1];
            float b00 = slope * fminf((float)(kj     - qi0), 0.f);
            float b10 = slope * fminf((float)(kj + 1 - qi0), 0.f);
            float b01 = slope * fminf((float)(kj     - qi1), 0.f);
            float b11 = slope * fminf((float)(kj + 1 - qi1), 0.f);
            sc[nt][0] = (mn0 != 0.f) ? -1e9f : sc[nt][0] + b00;
            sc[nt][1] = (mn1 != 0.f) ? -1e9f : sc[nt][1] + b10;
            sc[nt][2] = (mn0 != 0.f) ? -1e9f : sc[nt][2] + b01;
            sc[nt][3] = (mn1 != 0.f) ? -1e9f : sc[nt][3] + b11;
        }

        // Online softmax (rows g and g+8; rows live in 4-lane quads)
        float mt0 = -1e30f, mt1 = -1e30f;
        #pragma unroll
        for (int nt = 0; nt < 4; nt++) {
            mt0 = fmaxf(mt0, fmaxf(sc[nt][0], sc[nt][1]));
            mt1 = fmaxf(mt1, fmaxf(sc[nt][2], sc[nt][3]));
        }
        mt0 = fmaxf(mt0, __shfl_xor_sync(0xffffffffu, mt0, 1));
        mt0 = fmaxf(mt0, __shfl_xor_sync(0xffffffffu, mt0, 2));
        mt1 = fmaxf(mt1, __shfl_xor_sync(0xffffffffu, mt1, 1));
        mt1 = fmaxf(mt1, __shfl_xor_sync(0xffffffffu, mt1, 2));
        float nm0 = fmaxf(m0r, mt0), nm1 = fmaxf(m1r, mt1);
        float corr0 = __expf(m0r - nm0), corr1 = __expf(m1r - nm1);
        float rs0 = 0.f, rs1 = 0.f;
        #pragma unroll
        for (int nt = 0; nt < 4; nt++) {
            sc[nt][0] = __expf(sc[nt][0] - nm0);
            sc[nt][1] = __expf(sc[nt][1] - nm0);
            sc[nt][2] = __expf(sc[nt][2] - nm1);
            sc[nt][3] = __expf(sc[nt][3] - nm1);
            rs0 += sc[nt][0] + sc[nt][1];
            rs1 += sc[nt][2] + sc[nt][3];
        }
        rs0 += __shfl_xor_sync(0xffffffffu, rs0, 1);
        rs0 += __shfl_xor_sync(0xffffffffu, rs0, 2);
        rs1 += __shfl_xor_sync(0xffffffffu, rs1, 1);
        rs1 += __shfl_xor_sync(0xffffffffu, rs1, 2);
        l0r = l0r * corr0 + rs0;  m0r = nm0;
        l1r = l1r * corr1 + rs1;  m1r = nm1;
        #pragma unroll
        for (int nt = 0; nt < 8; nt++) {
            oc[nt][0] *= corr0; oc[nt][1] *= corr0;
            oc[nt][2] *= corr1; oc[nt][3] *= corr1;
        }

        // O += P V  (P repacked in registers; 2 k16 steps over 32 keys)
        #pragma unroll
        for (int ks = 0; ks < 2; ks++) {
            unsigned pah[4], pal[4];
            cvt_hilo2(sc[2*ks][0],   sc[2*ks][1],   pah[0], pal[0]);
            cvt_hilo2(sc[2*ks][2],   sc[2*ks][3],   pah[1], pal[1]);
            cvt_hilo2(sc[2*ks+1][0], sc[2*ks+1][1], pah[2], pal[2]);
            cvt_hilo2(sc[2*ks+1][2], sc[2*ks+1][3], pah[3], pal[3]);
            #pragma unroll
            for (int nt = 0; nt < 8; nt++) {
                int w = (nt * 8 + g) * 20 + ks * 8 + c;
                unsigned vbh[2] = { Vhw[w], Vhw[w + 4] };
                unsigned vbl[2] = { Vlw[w], Vlw[w + 4] };
                mma16(oc[nt], pah, vbh);
                mma16(oc[nt], pah, vbl);
                mma16(oc[nt], pal, vbh);
            }
        }
    }

    // Epilogue: normalize, write ctx bf16 hi/lo at [b][s][h*64+d]
    float inv0 = 1.f / l0r, inv1 = 1.f / l1r;
    size_t base0 = ((size_t)b * SS + qi0) * DD + h * HD;
    size_t base1 = ((size_t)b * SS + qi1) * DD + h * HD;
    #pragma unroll
    for (int nt = 0; nt < 8; nt++) {
        int d = nt * 8 + 2 * c;
        unsigned hp, lp;
        cvt_hilo2(oc[nt][0] * inv0, oc[nt][1] * inv0, hp, lp);
        *(unsigned*)&g_ctxh[base0 + d] = hp;
        *(unsigned*)&g_ctxl[base0 + d] = lp;
        cvt_hilo2(oc[nt][2] * inv1, oc[nt][3] * inv1, hp, lp);
        *(unsigned*)&g_ctxh[base1 + d] = hp;
        *(unsigned*)&g_ctxl[base1 + d] = lp;
    }
}

// ---------------------------------------------------------------------------
extern "C" void kernel_launch(void* const* d_in, const int* in_sizes, int n_in,
                              void* d_out, int out_size)
{
    const float* q    = (const float*)d_in[0];
    const float* k    = (const float*)d_in[1];
    const float* v    = (const float*)d_in[2];
    const int*   mask = (const int*)d_in[3];
    const float* Wq   = (const float*)d_in[4];
    const float* Wout = (const float*)d_in[5];
    float* out = (float*)d_out;

    cudaFuncSetAttribute(attn_kernel, cudaFuncAttributeMaxDynamicSharedMemorySize,
                         AT_SMEM);
    cudaFuncSetAttribute(proj_mm, cudaFuncAttributeMaxDynamicSharedMemorySize,
                         MMSMEM);
    cudaFuncSetAttribute(out_mm, cudaFuncAttributeMaxDynamicSharedMemorySize,
                         MMSMEM);

    // 1) fp32 -> bf16 hi/lo conversions (z-batched)
    conv_x<<<dim3(4096, 1, 3), 256>>>((const float4*)q, (const float4*)k,
                                      (const float4*)v);
    conv_w<<<dim3(1024, 1, 2), 256>>>((const float4*)Wq, (const float4*)Wout);

    // 2) Q/K/V projections (all use Wq, faithful to the reference)
    proj_mm<<<dim3(8, 32, 3), 512, MMSMEM>>>();

    // 3) Tensor-core flash attention with ALiBi (2 CTAs/SM)
    attn_kernel<<<dim3(8, 64), 256, AT_SMEM>>>(mask);

    // 4) Output projection
    out_mm<<<dim3(8, 32), 512, MMSMEM>>>(out);
}